// round 11
// baseline (speedup 1.0000x reference)
#include <cuda_runtime.h>
#include <cuda_fp16.h>
#include <math.h>
#include <stdint.h>

#define NTOK 8192
#define DIM 512
#define DFFV 1024
#define NE 8
#define TM 128
#define MAXTILES 136

// ---------------- device scratch ----------------
__device__ int   g_cnt[NE];
__device__ int   g_toff[NE + 1];
__device__ int   g_pair[2 * NTOK];        // token -> (id1, id2)
__device__ float g_wt  [2 * NTOK];        // token -> (w1, w2)
__device__ __half g_x  [(size_t)NE * NTOK * DIM];       // gathered x fp16
__device__ __half g_w1 [(size_t)NE * 2 * DFFV * DIM];   // W1^T fp16
__device__ __half g_w2 [(size_t)NE * DIM * DFFV];       // W2^T fp16
__device__ __half g_a  [(size_t)NE * NTOK * DFFV];      // act fp16
__device__ float  g_o  [(size_t)NE * NTOK * DIM];       // raw GEMM2 out

// ---------------- helpers ----------------
__device__ __forceinline__ uint32_t smem_u32(const void* p) {
    uint32_t a;
    asm("{ .reg .u64 t; cvta.to.shared.u64 t, %1; cvt.u32.u64 %0, t; }" : "=r"(a) : "l"(p));
    return a;
}
#define CPA16(sa, ga) asm volatile("cp.async.cg.shared.global [%0], [%1], 16;"::"r"(sa),"l"(ga):"memory")
#define CPA_COMMIT()  asm volatile("cp.async.commit_group;":::"memory")
#define CPA_WAIT2()   asm volatile("cp.async.wait_group 2;":::"memory")

#define LDSM_X4(r, addr) \
    asm volatile("ldmatrix.sync.aligned.m8n8.x4.shared.b16 {%0,%1,%2,%3}, [%4];" \
        : "=r"((r)[0]), "=r"((r)[1]), "=r"((r)[2]), "=r"((r)[3]) : "r"(addr))

#define MMA_F16(d, a, b0, b1) \
    asm volatile("mma.sync.aligned.m16n8k16.row.col.f32.f16.f16.f32 " \
        "{%0,%1,%2,%3},{%4,%5,%6,%7},{%8,%9},{%0,%1,%2,%3};" \
        : "+f"((d)[0]), "+f"((d)[1]), "+f"((d)[2]), "+f"((d)[3]) \
        : "r"((a)[0]), "r"((a)[1]), "r"((a)[2]), "r"((a)[3]), "r"(b0), "r"(b1))

__device__ __forceinline__ uint32_t sw64(uint32_t off) {
    return off ^ ((off >> 3) & 0x30);
}

// ---------------- K0: zero counters ----------------
__global__ void k_zero() {
    if (threadIdx.x < NE) g_cnt[threadIdx.x] = 0;
}

// ---------------- K1: gating + fused x->fp16 scatter ----------------
__global__ __launch_bounds__(256) void k_gate(const float* __restrict__ x,
                                              const float* __restrict__ Wg,
                                              const float* __restrict__ bg) {
    __shared__ float wgsT[NE][DIM];
    int t = threadIdx.x;
    for (int i = t; i < DIM * NE; i += 256) wgsT[i & 7][i >> 3] = Wg[i];
    __syncthreads();

    int warp = t >> 5, lane = t & 31;
    int tok = blockIdx.x * 8 + warp;

    float acc[NE];
#pragma unroll
    for (int e = 0; e < NE; e++) acc[e] = 0.f;
    const float4* xr = (const float4*)(x + (size_t)tok * DIM);
    float4 xv[4];
#pragma unroll
    for (int j = 0; j < 4; j++) {
        xv[j] = xr[lane + j * 32];
        int d = (lane + j * 32) * 4;
#pragma unroll
        for (int e = 0; e < NE; e++) {
            float4 w = *(const float4*)&wgsT[e][d];
            acc[e] += xv[j].x * w.x + xv[j].y * w.y + xv[j].z * w.z + xv[j].w * w.w;
        }
    }
#pragma unroll
    for (int e = 0; e < NE; e++)
#pragma unroll
        for (int o = 16; o; o >>= 1) acc[e] += __shfl_xor_sync(0xFFFFFFFFu, acc[e], o);

    int id1 = 0, id2 = 0;
    if (lane == 0) {
        float lg[NE];
#pragma unroll
        for (int e = 0; e < NE; e++) lg[e] = acc[e] + bg[e];
        int i1 = 0;
#pragma unroll
        for (int e = 1; e < NE; e++) if (lg[e] > lg[i1]) i1 = e;
        int i2 = (i1 == 0) ? 1 : 0;
#pragma unroll
        for (int e = 0; e < NE; e++) if (e != i1 && lg[e] > lg[i2]) i2 = e;
        float tt = expf(lg[i2] - lg[i1]);
        float w1 = 1.f / (1.f + tt);
        float w2 = tt / (1.f + tt);
        int p1 = atomicAdd(&g_cnt[i1], 1);
        int p2 = atomicAdd(&g_cnt[i2], 1);
        id1 = i1 * NTOK + p1;
        id2 = i2 * NTOK + p2;
        g_pair[2 * tok] = id1; g_pair[2 * tok + 1] = id2;
        g_wt[2 * tok] = w1;    g_wt[2 * tok + 1] = w2;
    }
    id1 = __shfl_sync(0xFFFFFFFFu, id1, 0);
    id2 = __shfl_sync(0xFFFFFFFFu, id2, 0);

#pragma unroll
    for (int j = 0; j < 4; j++) {
        __half h[4] = {__float2half(xv[j].x), __float2half(xv[j].y),
                       __float2half(xv[j].z), __float2half(xv[j].w)};
        int c = (lane + j * 32) * 4;
        *(uint2*)(g_x + (size_t)id1 * DIM + c) = *(uint2*)h;
        *(uint2*)(g_x + (size_t)id2 * DIM + c) = *(uint2*)h;
    }
}

// ---------------- K2: tile scan ----------------
__global__ void k_scan() {
    int tt = 0;
    for (int e = 0; e < NE; e++) {
        g_toff[e] = tt;
        tt += (g_cnt[e] + TM - 1) / TM;
    }
    g_toff[NE] = tt;
}

// ---------------- K3/K4: weight transpose + single fp16 ----------------
__global__ void k_conv_w1(const float* __restrict__ W1) {
    __shared__ float ts[32][33];
    int e = blockIdx.z, n0 = blockIdx.x * 32, k0 = blockIdx.y * 32;
    int tx = threadIdx.x, ty = threadIdx.y;
    const float* src = W1 + (size_t)e * DIM * 2 * DFFV;
#pragma unroll
    for (int i = 0; i < 4; i++)
        ts[ty + i * 8][tx] = src[(size_t)(k0 + ty + i * 8) * 2 * DFFV + n0 + tx];
    __syncthreads();
#pragma unroll
    for (int i = 0; i < 4; i++) {
        float v = ts[tx][ty + i * 8];
        size_t o = (size_t)e * 2 * DFFV * DIM + (size_t)(n0 + ty + i * 8) * DIM + k0 + tx;
        g_w1[o] = __float2half(v);
    }
}
__global__ void k_conv_w2(const float* __restrict__ W2) {
    __shared__ float ts[32][33];
    int e = blockIdx.z, d0 = blockIdx.x * 32, f0 = blockIdx.y * 32;
    int tx = threadIdx.x, ty = threadIdx.y;
    const float* src = W2 + (size_t)e * DFFV * DIM;
#pragma unroll
    for (int i = 0; i < 4; i++)
        ts[ty + i * 8][tx] = src[(size_t)(f0 + ty + i * 8) * DIM + d0 + tx];
    __syncthreads();
#pragma unroll
    for (int i = 0; i < 4; i++) {
        float v = ts[tx][ty + i * 8];
        size_t o = (size_t)e * DIM * DFFV + (size_t)(d0 + ty + i * 8) * DFFV + f0 + tx;
        g_w2[o] = __float2half(v);
    }
}

// ==================== GEMM core ====================
// CTA tile 128x128, BK=32, 4 stages, wait_group 2
// 4 warps (2x2), warp tile 64x64 -> acc[4][8][4], 2 CTAs/SM
#define ST_A  0
#define ST_B  8192
#define ST_STRIDE 16384
#define NSTAGE 4

__device__ __forceinline__ void compute_chunk(uint32_t sbase, int stage,
                                              int wm, int wn, int lane,
                                              float acc[4][8][4]) {
    uint32_t aOff = sbase + stage * ST_STRIDE + ST_A;
    uint32_t bOff = sbase + stage * ST_STRIDE + ST_B;
    int lr = lane & 15, lh = lane >> 4;
#pragma unroll
    for (int ks = 0; ks < 2; ks++) {
        uint32_t bh[16];
#pragma unroll
        for (int jp = 0; jp < 4; jp++) {
            uint32_t o = sw64((uint32_t)(wn * 64 + jp * 16 + lr) * 64 + ks * 32 + lh * 16);
            LDSM_X4(&bh[jp * 4], bOff + o);
        }
#pragma unroll
        for (int i = 0; i < 4; i++) {
            uint32_t o = sw64((uint32_t)(wm * 64 + i * 16 + lr) * 64 + ks * 32 + lh * 16);
            uint32_t af[4];
            LDSM_X4(af, aOff + o);
#pragma unroll
            for (int j = 0; j < 8; j++) {
                int jp = j >> 1, idx = j & 1;
                MMA_F16(acc[i][j], af, bh[jp * 4 + idx], bh[jp * 4 + idx + 2]);
            }
        }
    }
}

// ---------------- K5: GEMM1 + SiLU*mul -> act fp16 ----------------
__global__ __launch_bounds__(128, 2) void k_mm1(const float* __restrict__ b1) {
    int tile = blockIdx.x;
    if (tile >= g_toff[NE]) return;
    int e = 0;
    while (tile >= g_toff[e + 1]) e++;
    int m0 = (tile - g_toff[e]) * TM;
    int cnt = g_cnt[e];
    int f0 = blockIdx.y * 64;
    int abase = e * NTOK + m0;

    extern __shared__ __align__(1024) char dsm[];
    __shared__ float sb1a[64], sb1g[64];
    uint32_t sbase = smem_u32(dsm);

    int tid = threadIdx.x, wid = tid >> 5, lane = tid & 31;
    int wm = wid >> 1, wn = wid & 1;

    if (tid < 64) sb1a[tid] = b1[(size_t)e * 2 * DFFV + f0 + tid];
    else          sb1g[tid - 64] = b1[(size_t)e * 2 * DFFV + DFFV + f0 + tid - 64];

    const __half* w1 = g_w1 + (size_t)e * 2 * DFFV * DIM;

    float acc[4][8][4];
#pragma unroll
    for (int i = 0; i < 4; i++)
#pragma unroll
        for (int j = 0; j < 8; j++)
#pragma unroll
            for (int q = 0; q < 4; q++) acc[i][j][q] = 0.f;

    auto load_chunk = [&](int stage, int c) {
        uint32_t base = sbase + stage * ST_STRIDE;
        int k0 = c * 32;
#pragma unroll
        for (int u = tid; u < 512; u += 128) {
            int r = u >> 2, cs = u & 3;
            uint32_t sw = sw64((uint32_t)r * 64 + cs * 16);
            CPA16(base + ST_A + sw, g_x + (size_t)(abase + r) * DIM + k0 + cs * 8);
            int nw = (r & 1) ? (DFFV + f0 + (r >> 1)) : (f0 + (r >> 1));
            CPA16(base + ST_B + sw, w1 + (size_t)nw * DIM + k0 + cs * 8);
        }
    };

    const int NC = DIM / 32;  // 16
    load_chunk(0, 0); CPA_COMMIT();
    load_chunk(1, 1); CPA_COMMIT();
    load_chunk(2, 2); CPA_COMMIT();
    CPA_WAIT2();
    __syncthreads();
    for (int c = 0; c < NC; c++) {
        if (c + 3 < NC) load_chunk((c + 3) % NSTAGE, c + 3);
        CPA_COMMIT();
        compute_chunk(sbase, c % NSTAGE, wm, wn, lane, acc);
        CPA_WAIT2();
        __syncthreads();
    }

    // bias + silu*mul in registers.
    // n = wn*64 + j*8 + (lane&3)*2 (+1): even n = a-col f=n>>1, odd n = g-col
    // fl = wn*32 + j*4 + (lane&3)
#pragma unroll
    for (int i = 0; i < 4; i++)
#pragma unroll
        for (int j = 0; j < 8; j++) {
            int fl = wn * 32 + j * 4 + (lane & 3);
            float ba = sb1a[fl], bg = sb1g[fl];
            float a0 = acc[i][j][0] + ba, gg0 = acc[i][j][1] + bg;
            float a1 = acc[i][j][2] + ba, gg1 = acc[i][j][3] + bg;
            acc[i][j][0] = gg0 * a0 / (1.f + __expf(-a0));
            acc[i][j][2] = gg1 * a1 / (1.f + __expf(-a1));
        }

    // staged store through smem [128][72] halfs, 16B coalesced writes
    __half* st = (__half*)dsm;
#pragma unroll
    for (int i = 0; i < 4; i++) {
        int r0 = wm * 64 + i * 16 + (lane >> 2);
#pragma unroll
        for (int j = 0; j < 8; j++) {
            int fl = wn * 32 + j * 4 + (lane & 3);
            st[r0 * 72 + fl] = __float2half(acc[i][j][0]);
            st[(r0 + 8) * 72 + fl] = __float2half(acc[i][j][2]);
        }
    }
    __syncthreads();
#pragma unroll
    for (int u = tid; u < 1024; u += 128) {
        int r = u >> 3, seg = u & 7;
        if (m0 + r < cnt) {
            *(uint4*)(g_a + (size_t)(abase + r) * DFFV + f0 + seg * 8) =
                *(uint4*)&st[r * 72 + seg * 8];
        }
    }
}

// ---------------- K6: GEMM2 (single fp16) -> g_o ----------------
__global__ __launch_bounds__(128, 2) void k_mm2() {
    int tile = blockIdx.x;
    if (tile >= g_toff[NE]) return;
    int e = 0;
    while (tile >= g_toff[e + 1]) e++;
    int m0 = (tile - g_toff[e]) * TM;
    int cnt = g_cnt[e];
    int c0 = blockIdx.y * 128;
    int abase = e * NTOK + m0;

    extern __shared__ __align__(1024) char dsm[];
    uint32_t sbase = smem_u32(dsm);

    int tid = threadIdx.x, wid = tid >> 5, lane = tid & 31;
    int wm = wid >> 1, wn = wid & 1;

    const __half* w2 = g_w2 + (size_t)e * DIM * DFFV;

    float acc[4][8][4];
#pragma unroll
    for (int i = 0; i < 4; i++)
#pragma unroll
        for (int j = 0; j < 8; j++)
#pragma unroll
            for (int q = 0; q < 4; q++) acc[i][j][q] = 0.f;

    auto load_chunk = [&](int stage, int c) {
        uint32_t base = sbase + stage * ST_STRIDE;
        int k0 = c * 32;
#pragma unroll
        for (int u = tid; u < 512; u += 128) {
            int r = u >> 2, cs = u & 3;
            uint32_t sw = sw64((uint32_t)r * 64 + cs * 16);
            CPA16(base + ST_A + sw, g_a + (size_t)(abase + r) * DFFV + k0 + cs * 8);
            CPA16(base + ST_B + sw, w2 + (size_t)(c0 + r) * DFFV + k0 + cs * 8);
        }
    };

    const int NC = DFFV / 32;  // 32
    load_chunk(0, 0); CPA_COMMIT();
    load_chunk(1, 1); CPA_COMMIT();
    load_chunk(2, 2); CPA_COMMIT();
    CPA_WAIT2();
    __syncthreads();
    for (int c = 0; c < NC; c++) {
        if (c + 3 < NC) load_chunk((c + 3) % NSTAGE, c + 3);
        CPA_COMMIT();
        compute_chunk(sbase, c % NSTAGE, wm, wn, lane, acc);
        CPA_WAIT2();
        __syncthreads();
    }

    // epilogue: raw float2 stores to g_o (no atomics)
#pragma unroll
    for (int i = 0; i < 4; i++) {
        int r0 = wm * 64 + i * 16 + (lane >> 2);
        int r1 = r0 + 8;
#pragma unroll
        for (int j = 0; j < 8; j++) {
            int nl = wn * 64 + j * 8 + (lane & 3) * 2;
            if (m0 + r0 < cnt) {
                float2 v = make_float2(acc[i][j][0], acc[i][j][1]);
                *(float2*)(g_o + (size_t)(abase + r0) * DIM + c0 + nl) = v;
            }
            if (m0 + r1 < cnt) {
                float2 v = make_float2(acc[i][j][2], acc[i][j][3]);
                *(float2*)(g_o + (size_t)(abase + r1) * DIM + c0 + nl) = v;
            }
        }
    }
}

// ---------------- K7: combine two expert rows per token ----------------
__global__ __launch_bounds__(256) void k_comb(const float* __restrict__ b2,
                                              float* __restrict__ out) {
    int tok = blockIdx.x * 2 + (threadIdx.x >> 7);
    int c = (threadIdx.x & 127) * 4;
    int id1 = g_pair[2 * tok], id2 = g_pair[2 * tok + 1];
    float w1 = g_wt[2 * tok], w2 = g_wt[2 * tok + 1];
    int e1 = id1 >> 13, e2 = id2 >> 13;
    float4 o1 = *(const float4*)(g_o + (size_t)id1 * DIM + c);
    float4 o2 = *(const float4*)(g_o + (size_t)id2 * DIM + c);
    float4 ba = *(const float4*)(b2 + (size_t)e1 * DIM + c);
    float4 bb = *(const float4*)(b2 + (size_t)e2 * DIM + c);
    float4 r;
    r.x = w1 * (o1.x + ba.x) + w2 * (o2.x + bb.x);
    r.y = w1 * (o1.y + ba.y) + w2 * (o2.y + bb.y);
    r.z = w1 * (o1.z + ba.z) + w2 * (o2.z + bb.z);
    r.w = w1 * (o1.w + ba.w) + w2 * (o2.w + bb.w);
    *(float4*)(out + (size_t)tok * DIM + c) = r;
}

// ---------------- launcher ----------------
extern "C" void kernel_launch(void* const* d_in, const int* in_sizes, int n_in,
                              void* d_out, int out_size) {
    const float* x  = (const float*)d_in[0];
    const float* Wg = (const float*)d_in[1];
    const float* bg = (const float*)d_in[2];
    const float* W1 = (const float*)d_in[3];
    const float* b1 = (const float*)d_in[4];
    const float* W2 = (const float*)d_in[5];
    const float* b2 = (const float*)d_in[6];
    float* out = (float*)d_out;

    const int SMEM = NSTAGE * ST_STRIDE;  // 64 KB
    cudaFuncSetAttribute(k_mm1, cudaFuncAttributeMaxDynamicSharedMemorySize, SMEM);
    cudaFuncSetAttribute(k_mm2, cudaFuncAttributeMaxDynamicSharedMemorySize, SMEM);

    k_zero<<<1, 32>>>();
    k_conv_w1<<<dim3(64, 16, NE), dim3(32, 8)>>>(W1);
    k_conv_w2<<<dim3(16, 32, NE), dim3(32, 8)>>>(W2);
    k_gate<<<NTOK / 8, 256>>>(x, Wg, bg);
    k_scan<<<1, 1>>>();
    k_mm1<<<dim3(MAXTILES, DFFV / 64), 128, SMEM>>>(b1);
    k_mm2<<<dim3(MAXTILES, DIM / 128), 128, SMEM>>>();
    k_comb<<<NTOK / 2, 256>>>(b2, out);
}

// round 13
// speedup vs baseline: 1.0787x; 1.0787x over previous
#include <cuda_runtime.h>
#include <cuda_fp16.h>
#include <math.h>
#include <stdint.h>

#define NTOK 8192
#define DIM 512
#define DFFV 1024
#define NE 8
#define TM 128
#define MAXTILES 136

// ---------------- device scratch ----------------
__device__ int   g_cnt[NE];
__device__ int   g_toff[NE + 1];
__device__ int   g_pair[2 * NTOK];        // token -> (id1, id2)
__device__ float g_wt  [2 * NTOK];        // token -> (w1, w2)
__device__ __half g_x  [(size_t)NE * NTOK * DIM];       // gathered x fp16
__device__ __half g_w1 [(size_t)NE * 2 * DFFV * DIM];   // W1^T fp16
__device__ __half g_w2 [(size_t)NE * DIM * DFFV];       // W2^T fp16
__device__ __half g_a  [(size_t)NE * NTOK * DFFV];      // act fp16
__device__ float  g_o  [(size_t)NE * NTOK * DIM];       // raw GEMM2 out

// ---------------- helpers ----------------
__device__ __forceinline__ uint32_t smem_u32(const void* p) {
    uint32_t a;
    asm("{ .reg .u64 t; cvta.to.shared.u64 t, %1; cvt.u32.u64 %0, t; }" : "=r"(a) : "l"(p));
    return a;
}
#define CPA16(sa, ga) asm volatile("cp.async.cg.shared.global [%0], [%1], 16;"::"r"(sa),"l"(ga):"memory")
#define CPA_COMMIT()  asm volatile("cp.async.commit_group;":::"memory")
#define CPA_WAIT2()   asm volatile("cp.async.wait_group 2;":::"memory")

#define LDSM_X4(r, addr) \
    asm volatile("ldmatrix.sync.aligned.m8n8.x4.shared.b16 {%0,%1,%2,%3}, [%4];" \
        : "=r"((r)[0]), "=r"((r)[1]), "=r"((r)[2]), "=r"((r)[3]) : "r"(addr))

#define MMA_F16(d, a, b0, b1) \
    asm volatile("mma.sync.aligned.m16n8k16.row.col.f32.f16.f16.f32 " \
        "{%0,%1,%2,%3},{%4,%5,%6,%7},{%8,%9},{%0,%1,%2,%3};" \
        : "+f"((d)[0]), "+f"((d)[1]), "+f"((d)[2]), "+f"((d)[3]) \
        : "r"((a)[0]), "r"((a)[1]), "r"((a)[2]), "r"((a)[3]), "r"(b0), "r"(b1))

__device__ __forceinline__ uint32_t sw64(uint32_t off) {
    return off ^ ((off >> 3) & 0x30);
}

// ---------------- K0: zero counters ----------------
__global__ void k_zero() {
    if (threadIdx.x < NE) g_cnt[threadIdx.x] = 0;
}

// ---------------- K1: gating + fused x->fp16 scatter (4 tokens/warp) ----------------
__global__ __launch_bounds__(256) void k_gate(const float* __restrict__ x,
                                              const float* __restrict__ Wg,
                                              const float* __restrict__ bg) {
    __shared__ float wgsT[NE][DIM];
    int t = threadIdx.x;
    for (int i = t; i < DIM * NE; i += 256) wgsT[i & 7][i >> 3] = Wg[i];
    __syncthreads();

    int warp = t >> 5, lane = t & 31;
    int tok0 = blockIdx.x * 32 + warp * 4;

    for (int tt = 0; tt < 4; tt++) {
        int tok = tok0 + tt;

        float acc[NE];
#pragma unroll
        for (int e = 0; e < NE; e++) acc[e] = 0.f;
        const float4* xr = (const float4*)(x + (size_t)tok * DIM);
        float4 xv[4];
#pragma unroll
        for (int j = 0; j < 4; j++) xv[j] = xr[lane + j * 32];
#pragma unroll
        for (int j = 0; j < 4; j++) {
            int d = (lane + j * 32) * 4;
#pragma unroll
            for (int e = 0; e < NE; e++) {
                float4 w = *(const float4*)&wgsT[e][d];
                acc[e] += xv[j].x * w.x + xv[j].y * w.y + xv[j].z * w.z + xv[j].w * w.w;
            }
        }
#pragma unroll
        for (int e = 0; e < NE; e++)
#pragma unroll
            for (int o = 16; o; o >>= 1) acc[e] += __shfl_xor_sync(0xFFFFFFFFu, acc[e], o);

        int id1 = 0, id2 = 0;
        if (lane == 0) {
            float lg[NE];
#pragma unroll
            for (int e = 0; e < NE; e++) lg[e] = acc[e] + bg[e];
            int i1 = 0;
#pragma unroll
            for (int e = 1; e < NE; e++) if (lg[e] > lg[i1]) i1 = e;
            int i2 = (i1 == 0) ? 1 : 0;
#pragma unroll
            for (int e = 0; e < NE; e++) if (e != i1 && lg[e] > lg[i2]) i2 = e;
            float tv = expf(lg[i2] - lg[i1]);
            float w1 = 1.f / (1.f + tv);
            float w2 = tv / (1.f + tv);
            int p1 = atomicAdd(&g_cnt[i1], 1);
            int p2 = atomicAdd(&g_cnt[i2], 1);
            id1 = i1 * NTOK + p1;
            id2 = i2 * NTOK + p2;
            g_pair[2 * tok] = id1; g_pair[2 * tok + 1] = id2;
            g_wt[2 * tok] = w1;    g_wt[2 * tok + 1] = w2;
        }
        id1 = __shfl_sync(0xFFFFFFFFu, id1, 0);
        id2 = __shfl_sync(0xFFFFFFFFu, id2, 0);

#pragma unroll
        for (int j = 0; j < 4; j++) {
            __half h[4] = {__float2half(xv[j].x), __float2half(xv[j].y),
                           __float2half(xv[j].z), __float2half(xv[j].w)};
            int c = (lane + j * 32) * 4;
            *(uint2*)(g_x + (size_t)id1 * DIM + c) = *(uint2*)h;
            *(uint2*)(g_x + (size_t)id2 * DIM + c) = *(uint2*)h;
        }
    }
}

// ---------------- K2: tile scan ----------------
__global__ void k_scan() {
    int tt = 0;
    for (int e = 0; e < NE; e++) {
        g_toff[e] = tt;
        tt += (g_cnt[e] + TM - 1) / TM;
    }
    g_toff[NE] = tt;
}

// ---------------- K3/K4: weight transpose + single fp16 ----------------
__global__ void k_conv_w1(const float* __restrict__ W1) {
    __shared__ float ts[32][33];
    int e = blockIdx.z, n0 = blockIdx.x * 32, k0 = blockIdx.y * 32;
    int tx = threadIdx.x, ty = threadIdx.y;
    const float* src = W1 + (size_t)e * DIM * 2 * DFFV;
#pragma unroll
    for (int i = 0; i < 4; i++)
        ts[ty + i * 8][tx] = src[(size_t)(k0 + ty + i * 8) * 2 * DFFV + n0 + tx];
    __syncthreads();
#pragma unroll
    for (int i = 0; i < 4; i++) {
        float v = ts[tx][ty + i * 8];
        size_t o = (size_t)e * 2 * DFFV * DIM + (size_t)(n0 + ty + i * 8) * DIM + k0 + tx;
        g_w1[o] = __float2half(v);
    }
}
__global__ void k_conv_w2(const float* __restrict__ W2) {
    __shared__ float ts[32][33];
    int e = blockIdx.z, d0 = blockIdx.x * 32, f0 = blockIdx.y * 32;
    int tx = threadIdx.x, ty = threadIdx.y;
    const float* src = W2 + (size_t)e * DFFV * DIM;
#pragma unroll
    for (int i = 0; i < 4; i++)
        ts[ty + i * 8][tx] = src[(size_t)(f0 + ty + i * 8) * DIM + d0 + tx];
    __syncthreads();
#pragma unroll
    for (int i = 0; i < 4; i++) {
        float v = ts[tx][ty + i * 8];
        size_t o = (size_t)e * DIM * DFFV + (size_t)(d0 + ty + i * 8) * DFFV + f0 + tx;
        g_w2[o] = __float2half(v);
    }
}

// ==================== GEMM core (R10-proven: 8 warps 2x4, warp tile 64x32) ====================
// tile 128x128, BK=32, 4 stages, wait_group 2
#define ST_A  0
#define ST_B  8192
#define ST_STRIDE 16384
#define NSTAGE 4

__device__ __forceinline__ void compute_chunk(uint32_t sbase, int stage,
                                              int wm, int wn, int lane,
                                              float acc[4][4][4]) {
    uint32_t aOff = sbase + stage * ST_STRIDE + ST_A;
    uint32_t bOff = sbase + stage * ST_STRIDE + ST_B;
    int lr = lane & 15, lh = lane >> 4;
#pragma unroll
    for (int ks = 0; ks < 2; ks++) {
        uint32_t bh[8];
#pragma unroll
        for (int jp = 0; jp < 2; jp++) {
            uint32_t o = sw64((uint32_t)(wn * 32 + jp * 16 + lr) * 64 + ks * 32 + lh * 16);
            LDSM_X4(&bh[jp * 4], bOff + o);
        }
#pragma unroll
        for (int i = 0; i < 4; i++) {
            uint32_t o = sw64((uint32_t)(wm * 64 + i * 16 + lr) * 64 + ks * 32 + lh * 16);
            uint32_t af[4];
            LDSM_X4(af, aOff + o);
#pragma unroll
            for (int j = 0; j < 4; j++) {
                int jp = j >> 1, idx = j & 1;
                MMA_F16(acc[i][j], af, bh[jp * 4 + idx], bh[jp * 4 + idx + 2]);
            }
        }
    }
}

// ---------------- K5: GEMM1 + SiLU*mul -> act fp16 ----------------
__global__ __launch_bounds__(256, 2) void k_mm1(const float* __restrict__ b1) {
    int tile = blockIdx.x;
    if (tile >= g_toff[NE]) return;
    int e = 0;
    while (tile >= g_toff[e + 1]) e++;
    int m0 = (tile - g_toff[e]) * TM;
    int cnt = g_cnt[e];
    int f0 = blockIdx.y * 64;
    int abase = e * NTOK + m0;

    extern __shared__ __align__(1024) char dsm[];
    __shared__ float sb1a[64], sb1g[64];
    uint32_t sbase = smem_u32(dsm);

    int tid = threadIdx.x, wid = tid >> 5, lane = tid & 31;
    int wm = wid >> 2, wn = wid & 3;

    if (tid < 64)       sb1a[tid] = b1[(size_t)e * 2 * DFFV + f0 + tid];
    else if (tid < 128) sb1g[tid - 64] = b1[(size_t)e * 2 * DFFV + DFFV + f0 + tid - 64];

    const __half* w1 = g_w1 + (size_t)e * 2 * DFFV * DIM;

    float acc[4][4][4];
#pragma unroll
    for (int i = 0; i < 4; i++)
#pragma unroll
        for (int j = 0; j < 4; j++)
#pragma unroll
            for (int q = 0; q < 4; q++) acc[i][j][q] = 0.f;

    auto load_chunk = [&](int stage, int c) {
        uint32_t base = sbase + stage * ST_STRIDE;
        int k0 = c * 32;
#pragma unroll
        for (int u = tid; u < 512; u += 256) {
            int r = u >> 2, cs = u & 3;
            uint32_t sw = sw64((uint32_t)r * 64 + cs * 16);
            CPA16(base + ST_A + sw, g_x + (size_t)(abase + r) * DIM + k0 + cs * 8);
            int nw = (r & 1) ? (DFFV + f0 + (r >> 1)) : (f0 + (r >> 1));
            CPA16(base + ST_B + sw, w1 + (size_t)nw * DIM + k0 + cs * 8);
        }
    };

    const int NC = DIM / 32;  // 16
    load_chunk(0, 0); CPA_COMMIT();
    load_chunk(1, 1); CPA_COMMIT();
    load_chunk(2, 2); CPA_COMMIT();
    CPA_WAIT2();
    __syncthreads();
    for (int c = 0; c < NC; c++) {
        if (c + 3 < NC) load_chunk((c + 3) % NSTAGE, c + 3);
        CPA_COMMIT();
        compute_chunk(sbase, c % NSTAGE, wm, wn, lane, acc);
        CPA_WAIT2();
        __syncthreads();
    }

    // bias + silu*mul in registers
#pragma unroll
    for (int i = 0; i < 4; i++)
#pragma unroll
        for (int j = 0; j < 4; j++) {
            int fl = wn * 16 + j * 4 + (lane & 3);
            float ba = sb1a[fl], bg = sb1g[fl];
            float a0 = acc[i][j][0] + ba, gg0 = acc[i][j][1] + bg;
            float a1 = acc[i][j][2] + ba, gg1 = acc[i][j][3] + bg;
            acc[i][j][0] = gg0 * a0 / (1.f + __expf(-a0));
            acc[i][j][2] = gg1 * a1 / (1.f + __expf(-a1));
        }

    // staged store through smem [128][72] halfs, 16B coalesced writes
    __half* st = (__half*)dsm;
#pragma unroll
    for (int i = 0; i < 4; i++) {
        int r0 = wm * 64 + i * 16 + (lane >> 2);
#pragma unroll
        for (int j = 0; j < 4; j++) {
            int fl = wn * 16 + j * 4 + (lane & 3);
            st[r0 * 72 + fl] = __float2half(acc[i][j][0]);
            st[(r0 + 8) * 72 + fl] = __float2half(acc[i][j][2]);
        }
    }
    __syncthreads();
#pragma unroll
    for (int u = tid; u < 1024; u += 256) {
        int r = u >> 3, seg = u & 7;
        if (m0 + r < cnt) {
            *(uint4*)(g_a + (size_t)(abase + r) * DFFV + f0 + seg * 8) =
                *(uint4*)&st[r * 72 + seg * 8];
        }
    }
}

// ---------------- K6: GEMM2 (single fp16) -> g_o ----------------
__global__ __launch_bounds__(256, 2) void k_mm2() {
    int tile = blockIdx.x;
    if (tile >= g_toff[NE]) return;
    int e = 0;
    while (tile >= g_toff[e + 1]) e++;
    int m0 = (tile - g_toff[e]) * TM;
    int cnt = g_cnt[e];
    int c0 = blockIdx.y * 128;
    int abase = e * NTOK + m0;

    extern __shared__ __align__(1024) char dsm[];
    uint32_t sbase = smem_u32(dsm);

    int tid = threadIdx.x, wid = tid >> 5, lane = tid & 31;
    int wm = wid >> 2, wn = wid & 3;

    const __half* w2 = g_w2 + (size_t)e * DIM * DFFV;

    float acc[4][4][4];
#pragma unroll
    for (int i = 0; i < 4; i++)
#pragma unroll
        for (int j = 0; j < 4; j++)
#pragma unroll
            for (int q = 0; q < 4; q++) acc[i][j][q] = 0.f;

    auto load_chunk = [&](int stage, int c) {
        uint32_t base = sbase + stage * ST_STRIDE;
        int k0 = c * 32;
#pragma unroll
        for (int u = tid; u < 512; u += 256) {
            int r = u >> 2, cs = u & 3;
            uint32_t sw = sw64((uint32_t)r * 64 + cs * 16);
            CPA16(base + ST_A + sw, g_a + (size_t)(abase + r) * DFFV + k0 + cs * 8);
            CPA16(base + ST_B + sw, w2 + (size_t)(c0 + r) * DFFV + k0 + cs * 8);
        }
    };

    const int NC = DFFV / 32;  // 32
    load_chunk(0, 0); CPA_COMMIT();
    load_chunk(1, 1); CPA_COMMIT();
    load_chunk(2, 2); CPA_COMMIT();
    CPA_WAIT2();
    __syncthreads();
    for (int c = 0; c < NC; c++) {
        if (c + 3 < NC) load_chunk((c + 3) % NSTAGE, c + 3);
        CPA_COMMIT();
        compute_chunk(sbase, c % NSTAGE, wm, wn, lane, acc);
        CPA_WAIT2();
        __syncthreads();
    }

    // epilogue: raw float2 stores to g_o (no atomics)
#pragma unroll
    for (int i = 0; i < 4; i++) {
        int r0 = wm * 64 + i * 16 + (lane >> 2);
        int r1 = r0 + 8;
#pragma unroll
        for (int j = 0; j < 4; j++) {
            int nl = wn * 32 + j * 8 + (lane & 3) * 2;
            if (m0 + r0 < cnt) {
                float2 v = make_float2(acc[i][j][0], acc[i][j][1]);
                *(float2*)(g_o + (size_t)(abase + r0) * DIM + c0 + nl) = v;
            }
            if (m0 + r1 < cnt) {
                float2 v = make_float2(acc[i][j][2], acc[i][j][3]);
                *(float2*)(g_o + (size_t)(abase + r1) * DIM + c0 + nl) = v;
            }
        }
    }
}

// ---------------- K7: combine two expert rows per token ----------------
__global__ __launch_bounds__(256) void k_comb(const float* __restrict__ b2,
                                              float* __restrict__ out) {
    int tok = blockIdx.x * 2 + (threadIdx.x >> 7);
    int c = (threadIdx.x & 127) * 4;
    int id1 = g_pair[2 * tok], id2 = g_pair[2 * tok + 1];
    float w1 = g_wt[2 * tok], w2 = g_wt[2 * tok + 1];
    int e1 = id1 >> 13, e2 = id2 >> 13;
    float4 o1 = *(const float4*)(g_o + (size_t)id1 * DIM + c);
    float4 o2 = *(const float4*)(g_o + (size_t)id2 * DIM + c);
    float4 ba = *(const float4*)(b2 + (size_t)e1 * DIM + c);
    float4 bb = *(const float4*)(b2 + (size_t)e2 * DIM + c);
    float4 r;
    r.x = w1 * (o1.x + ba.x) + w2 * (o2.x + bb.x);
    r.y = w1 * (o1.y + ba.y) + w2 * (o2.y + bb.y);
    r.z = w1 * (o1.z + ba.z) + w2 * (o2.z + bb.z);
    r.w = w1 * (o1.w + ba.w) + w2 * (o2.w + bb.w);
    *(float4*)(out + (size_t)tok * DIM + c) = r;
}

// ---------------- launcher ----------------
extern "C" void kernel_launch(void* const* d_in, const int* in_sizes, int n_in,
                              void* d_out, int out_size) {
    const float* x  = (const float*)d_in[0];
    const float* Wg = (const float*)d_in[1];
    const float* bg = (const float*)d_in[2];
    const float* W1 = (const float*)d_in[3];
    const float* b1 = (const float*)d_in[4];
    const float* W2 = (const float*)d_in[5];
    const float* b2 = (const float*)d_in[6];
    float* out = (float*)d_out;

    const int SMEM = NSTAGE * ST_STRIDE;  // 64 KB
    cudaFuncSetAttribute(k_mm1, cudaFuncAttributeMaxDynamicSharedMemorySize, SMEM);
    cudaFuncSetAttribute(k_mm2, cudaFuncAttributeMaxDynamicSharedMemorySize, SMEM);

    k_zero<<<1, 32>>>();
    k_conv_w1<<<dim3(64, 16, NE), dim3(32, 8)>>>(W1);
    k_conv_w2<<<dim3(16, 32, NE), dim3(32, 8)>>>(W2);
    k_gate<<<NTOK / 32, 256>>>(x, Wg, bg);
    k_scan<<<1, 1>>>();
    k_mm1<<<dim3(MAXTILES, DFFV / 64), 256, SMEM>>>(b1);
    k_mm2<<<dim3(MAXTILES, DIM / 128), 256, SMEM>>>();
    k_comb<<<NTOK / 2, 256>>>(b2, out);
}

// round 15
// speedup vs baseline: 1.0996x; 1.0193x over previous
#include <cuda_runtime.h>
#include <cuda_fp16.h>
#include <math.h>
#include <stdint.h>

#define NTOK 8192
#define DIM 512
#define DFFV 1024
#define NE 8
#define TM 128
#define MAXTILES 136

// ---------------- device scratch ----------------
__device__ int   g_cnt[NE];
__device__ int   g_tokid[NE * NTOK];      // id -> token
__device__ float g_wtid [NE * NTOK];      // id -> routing weight
__device__ __half g_x  [(size_t)NE * NTOK * DIM];       // gathered x fp16
__device__ __half g_w1 [(size_t)NE * 2 * DFFV * DIM];   // W1^T fp16
__device__ __half g_w2 [(size_t)NE * DIM * DFFV];       // W2^T fp16
__device__ __half g_a  [(size_t)NE * NTOK * DFFV];      // act fp16

// ---------------- helpers ----------------
__device__ __forceinline__ uint32_t smem_u32(const void* p) {
    uint32_t a;
    asm("{ .reg .u64 t; cvta.to.shared.u64 t, %1; cvt.u32.u64 %0, t; }" : "=r"(a) : "l"(p));
    return a;
}
#define CPA16(sa, ga) asm volatile("cp.async.cg.shared.global [%0], [%1], 16;"::"r"(sa),"l"(ga):"memory")
#define CPA_COMMIT()  asm volatile("cp.async.commit_group;":::"memory")
#define CPA_WAIT2()   asm volatile("cp.async.wait_group 2;":::"memory")

#define LDSM_X4(r, addr) \
    asm volatile("ldmatrix.sync.aligned.m8n8.x4.shared.b16 {%0,%1,%2,%3}, [%4];" \
        : "=r"((r)[0]), "=r"((r)[1]), "=r"((r)[2]), "=r"((r)[3]) : "r"(addr))

#define MMA_F16(d, a, b0, b1) \
    asm volatile("mma.sync.aligned.m16n8k16.row.col.f32.f16.f16.f32 " \
        "{%0,%1,%2,%3},{%4,%5,%6,%7},{%8,%9},{%0,%1,%2,%3};" \
        : "+f"((d)[0]), "+f"((d)[1]), "+f"((d)[2]), "+f"((d)[3]) \
        : "r"((a)[0]), "r"((a)[1]), "r"((a)[2]), "r"((a)[3]), "r"(b0), "r"(b1))

__device__ __forceinline__ uint32_t sw64(uint32_t off) {
    return off ^ ((off >> 3) & 0x30);
}

// locate expert + tile base from g_cnt (replaces k_scan)
__device__ __forceinline__ bool tile_lookup(int tile, int& e, int& m0, int& cnt) {
    int base = 0;
    for (e = 0; e < NE; e++) {
        int c = g_cnt[e];
        int nt = (c + TM - 1) / TM;
        if (tile < base + nt) { m0 = (tile - base) * TM; cnt = c; return true; }
        base += nt;
    }
    return false;
}

// ---------------- K0: zero out + counters ----------------
__global__ void k_zero(float* __restrict__ out, int n) {
    if (blockIdx.x == 0 && threadIdx.x < NE) g_cnt[threadIdx.x] = 0;
    int i = blockIdx.x * blockDim.x + threadIdx.x;
    int stride = gridDim.x * blockDim.x;
    for (; i < n; i += stride) out[i] = 0.f;
}

// ---------------- K1: gating + fused x->fp16 scatter (R10-proven form) ----------------
__global__ __launch_bounds__(256) void k_gate(const float* __restrict__ x,
                                              const float* __restrict__ Wg,
                                              const float* __restrict__ bg) {
    __shared__ float wgsT[NE][DIM];
    int t = threadIdx.x;
    for (int i = t; i < DIM * NE; i += 256) wgsT[i & 7][i >> 3] = Wg[i];
    __syncthreads();

    int warp = t >> 5, lane = t & 31;
    int tok = blockIdx.x * 8 + warp;

    float acc[NE];
#pragma unroll
    for (int e = 0; e < NE; e++) acc[e] = 0.f;
    const float4* xr = (const float4*)(x + (size_t)tok * DIM);
    float4 xv[4];
#pragma unroll
    for (int j = 0; j < 4; j++) {
        xv[j] = xr[lane + j * 32];
        int d = (lane + j * 32) * 4;
#pragma unroll
        for (int e = 0; e < NE; e++) {
            float4 w = *(const float4*)&wgsT[e][d];
            acc[e] += xv[j].x * w.x + xv[j].y * w.y + xv[j].z * w.z + xv[j].w * w.w;
        }
    }
#pragma unroll
    for (int e = 0; e < NE; e++)
#pragma unroll
        for (int o = 16; o; o >>= 1) acc[e] += __shfl_xor_sync(0xFFFFFFFFu, acc[e], o);

    int id1 = 0, id2 = 0;
    if (lane == 0) {
        float lg[NE];
#pragma unroll
        for (int e = 0; e < NE; e++) lg[e] = acc[e] + bg[e];
        int i1 = 0;
#pragma unroll
        for (int e = 1; e < NE; e++) if (lg[e] > lg[i1]) i1 = e;
        int i2 = (i1 == 0) ? 1 : 0;
#pragma unroll
        for (int e = 0; e < NE; e++) if (e != i1 && lg[e] > lg[i2]) i2 = e;
        float tt = expf(lg[i2] - lg[i1]);
        float w1 = 1.f / (1.f + tt);
        float w2 = tt / (1.f + tt);
        int p1 = atomicAdd(&g_cnt[i1], 1);
        int p2 = atomicAdd(&g_cnt[i2], 1);
        id1 = i1 * NTOK + p1;
        id2 = i2 * NTOK + p2;
        g_tokid[id1] = tok; g_wtid[id1] = w1;
        g_tokid[id2] = tok; g_wtid[id2] = w2;
    }
    id1 = __shfl_sync(0xFFFFFFFFu, id1, 0);
    id2 = __shfl_sync(0xFFFFFFFFu, id2, 0);

#pragma unroll
    for (int j = 0; j < 4; j++) {
        __half h[4] = {__float2half(xv[j].x), __float2half(xv[j].y),
                       __float2half(xv[j].z), __float2half(xv[j].w)};
        int c = (lane + j * 32) * 4;
        *(uint2*)(g_x + (size_t)id1 * DIM + c) = *(uint2*)h;
        *(uint2*)(g_x + (size_t)id2 * DIM + c) = *(uint2*)h;
    }
}

// ---------------- K2/K3: weight transpose + single fp16 ----------------
__global__ void k_conv_w1(const float* __restrict__ W1) {
    __shared__ float ts[32][33];
    int e = blockIdx.z, n0 = blockIdx.x * 32, k0 = blockIdx.y * 32;
    int tx = threadIdx.x, ty = threadIdx.y;
    const float* src = W1 + (size_t)e * DIM * 2 * DFFV;
#pragma unroll
    for (int i = 0; i < 4; i++)
        ts[ty + i * 8][tx] = src[(size_t)(k0 + ty + i * 8) * 2 * DFFV + n0 + tx];
    __syncthreads();
#pragma unroll
    for (int i = 0; i < 4; i++) {
        float v = ts[tx][ty + i * 8];
        size_t o = (size_t)e * 2 * DFFV * DIM + (size_t)(n0 + ty + i * 8) * DIM + k0 + tx;
        g_w1[o] = __float2half(v);
    }
}
__global__ void k_conv_w2(const float* __restrict__ W2) {
    __shared__ float ts[32][33];
    int e = blockIdx.z, d0 = blockIdx.x * 32, f0 = blockIdx.y * 32;
    int tx = threadIdx.x, ty = threadIdx.y;
    const float* src = W2 + (size_t)e * DFFV * DIM;
#pragma unroll
    for (int i = 0; i < 4; i++)
        ts[ty + i * 8][tx] = src[(size_t)(f0 + ty + i * 8) * DIM + d0 + tx];
    __syncthreads();
#pragma unroll
    for (int i = 0; i < 4; i++) {
        float v = ts[tx][ty + i * 8];
        size_t o = (size_t)e * DIM * DFFV + (size_t)(d0 + ty + i * 8) * DFFV + f0 + tx;
        g_w2[o] = __float2half(v);
    }
}

// ==================== GEMM core (R10-proven: 8 warps 2x4, warp tile 64x32) ====================
// tile 128x128, BK=32, 4 stages, wait_group 2
#define ST_A  0
#define ST_B  8192
#define ST_STRIDE 16384
#define NSTAGE 4

__device__ __forceinline__ void compute_chunk(uint32_t sbase, int stage,
                                              int wm, int wn, int lane,
                                              float acc[4][4][4]) {
    uint32_t aOff = sbase + stage * ST_STRIDE + ST_A;
    uint32_t bOff = sbase + stage * ST_STRIDE + ST_B;
    int lr = lane & 15, lh = lane >> 4;
#pragma unroll
    for (int ks = 0; ks < 2; ks++) {
        uint32_t bh[8];
#pragma unroll
        for (int jp = 0; jp < 2; jp++) {
            uint32_t o = sw64((uint32_t)(wn * 32 + jp * 16 + lr) * 64 + ks * 32 + lh * 16);
            LDSM_X4(&bh[jp * 4], bOff + o);
        }
#pragma unroll
        for (int i = 0; i < 4; i++) {
            uint32_t o = sw64((uint32_t)(wm * 64 + i * 16 + lr) * 64 + ks * 32 + lh * 16);
            uint32_t af[4];
            LDSM_X4(af, aOff + o);
#pragma unroll
            for (int j = 0; j < 4; j++) {
                int jp = j >> 1, idx = j & 1;
                MMA_F16(acc[i][j], af, bh[jp * 4 + idx], bh[jp * 4 + idx + 2]);
            }
        }
    }
}

// ---------------- K4: GEMM1 + SiLU*mul -> act fp16 ----------------
__global__ __launch_bounds__(256, 2) void k_mm1(const float* __restrict__ b1) {
    int e, m0, cnt;
    if (!tile_lookup(blockIdx.x, e, m0, cnt)) return;
    int f0 = blockIdx.y * 64;
    int abase = e * NTOK + m0;

    extern __shared__ __align__(1024) char dsm[];
    __shared__ float sb1a[64], sb1g[64];
    uint32_t sbase = smem_u32(dsm);

    int tid = threadIdx.x, wid = tid >> 5, lane = tid & 31;
    int wm = wid >> 2, wn = wid & 3;

    if (tid < 64)       sb1a[tid] = b1[(size_t)e * 2 * DFFV + f0 + tid];
    else if (tid < 128) sb1g[tid - 64] = b1[(size_t)e * 2 * DFFV + DFFV + f0 + tid - 64];

    const __half* w1 = g_w1 + (size_t)e * 2 * DFFV * DIM;

    float acc[4][4][4];
#pragma unroll
    for (int i = 0; i < 4; i++)
#pragma unroll
        for (int j = 0; j < 4; j++)
#pragma unroll
            for (int q = 0; q < 4; q++) acc[i][j][q] = 0.f;

    auto load_chunk = [&](int stage, int c) {
        uint32_t base = sbase + stage * ST_STRIDE;
        int k0 = c * 32;
#pragma unroll
        for (int u = tid; u < 512; u += 256) {
            int r = u >> 2, cs = u & 3;
            uint32_t sw = sw64((uint32_t)r * 64 + cs * 16);
            CPA16(base + ST_A + sw, g_x + (size_t)(abase + r) * DIM + k0 + cs * 8);
            int nw = (r & 1) ? (DFFV + f0 + (r >> 1)) : (f0 + (r >> 1));
            CPA16(base + ST_B + sw, w1 + (size_t)nw * DIM + k0 + cs * 8);
        }
    };

    const int NC = DIM / 32;  // 16
    load_chunk(0, 0); CPA_COMMIT();
    load_chunk(1, 1); CPA_COMMIT();
    load_chunk(2, 2); CPA_COMMIT();
    CPA_WAIT2();
    __syncthreads();
    for (int c = 0; c < NC; c++) {
        if (c + 3 < NC) load_chunk((c + 3) % NSTAGE, c + 3);
        CPA_COMMIT();
        compute_chunk(sbase, c % NSTAGE, wm, wn, lane, acc);
        CPA_WAIT2();
        __syncthreads();
    }

    // bias + silu*mul in registers
#pragma unroll
    for (int i = 0; i < 4; i++)
#pragma unroll
        for (int j = 0; j < 4; j++) {
            int fl = wn * 16 + j * 4 + (lane & 3);
            float ba = sb1a[fl], bg = sb1g[fl];
            float a0 = acc[i][j][0] + ba, gg0 = acc[i][j][1] + bg;
            float a1 = acc[i][j][2] + ba, gg1 = acc[i][j][3] + bg;
            acc[i][j][0] = gg0 * a0 / (1.f + __expf(-a0));
            acc[i][j][2] = gg1 * a1 / (1.f + __expf(-a1));
        }

    // staged store through smem [128][72] halfs, 16B coalesced writes
    __half* st = (__half*)dsm;
#pragma unroll
    for (int i = 0; i < 4; i++) {
        int r0 = wm * 64 + i * 16 + (lane >> 2);
#pragma unroll
        for (int j = 0; j < 4; j++) {
            int fl = wn * 16 + j * 4 + (lane & 3);
            st[r0 * 72 + fl] = __float2half(acc[i][j][0]);
            st[(r0 + 8) * 72 + fl] = __float2half(acc[i][j][2]);
        }
    }
    __syncthreads();
#pragma unroll
    for (int u = tid; u < 1024; u += 256) {
        int r = u >> 3, seg = u & 7;
        if (m0 + r < cnt) {
            *(uint4*)(g_a + (size_t)(abase + r) * DFFV + f0 + seg * 8) =
                *(uint4*)&st[r * 72 + seg * 8];
        }
    }
}

// ---------------- K5: GEMM2 + fused weighted scatter (2 atomics/elem, deterministic) ----------------
__global__ __launch_bounds__(256, 2) void k_mm2(const float* __restrict__ b2,
                                                float* __restrict__ out) {
    int e, m0, cnt;
    if (!tile_lookup(blockIdx.x, e, m0, cnt)) return;
    int c0 = blockIdx.y * 128;
    int abase = e * NTOK + m0;

    extern __shared__ __align__(1024) char dsm[];
    __shared__ float sb2[128];
    __shared__ int   s_tok[128];
    __shared__ float s_wt[128];
    uint32_t sbase = smem_u32(dsm);

    int tid = threadIdx.x, wid = tid >> 5, lane = tid & 31;
    int wm = wid >> 2, wn = wid & 3;

    if (tid < 128) {
        sb2[tid] = b2[(size_t)e * DIM + c0 + tid];
        int ok = (m0 + tid) < cnt;
        s_tok[tid] = ok ? g_tokid[abase + tid] : -1;
        s_wt[tid]  = ok ? g_wtid[abase + tid] : 0.f;
    }

    const __half* w2 = g_w2 + (size_t)e * DIM * DFFV;

    float acc[4][4][4];
#pragma unroll
    for (int i = 0; i < 4; i++)
#pragma unroll
        for (int j = 0; j < 4; j++)
#pragma unroll
            for (int q = 0; q < 4; q++) acc[i][j][q] = 0.f;

    auto load_chunk = [&](int stage, int c) {
        uint32_t base = sbase + stage * ST_STRIDE;
        int k0 = c * 32;
#pragma unroll
        for (int u = tid; u < 512; u += 256) {
            int r = u >> 2, cs = u & 3;
            uint32_t sw = sw64((uint32_t)r * 64 + cs * 16);
            CPA16(base + ST_A + sw, g_a + (size_t)(abase + r) * DFFV + k0 + cs * 8);
            CPA16(base + ST_B + sw, w2 + (size_t)(c0 + r) * DFFV + k0 + cs * 8);
        }
    };

    const int NC = DFFV / 32;  // 32
    load_chunk(0, 0); CPA_COMMIT();
    load_chunk(1, 1); CPA_COMMIT();
    load_chunk(2, 2); CPA_COMMIT();
    CPA_WAIT2();
    __syncthreads();
    for (int c = 0; c < NC; c++) {
        if (c + 3 < NC) load_chunk((c + 3) % NSTAGE, c + 3);
        CPA_COMMIT();
        compute_chunk(sbase, c % NSTAGE, wm, wn, lane, acc);
        CPA_WAIT2();
        __syncthreads();
    }

    // epilogue: (acc + b2) * wt, atomicAdd to out (exactly 2 adds/elem -> deterministic)
#pragma unroll
    for (int i = 0; i < 4; i++) {
        int r0 = wm * 64 + i * 16 + (lane >> 2);
        int r1 = r0 + 8;
        int tok0 = s_tok[r0], tok1 = s_tok[r1];
        float wt0 = s_wt[r0], wt1 = s_wt[r1];
#pragma unroll
        for (int j = 0; j < 4; j++) {
            int nl = wn * 32 + j * 8 + (lane & 3) * 2;
            float bA = sb2[nl], bB = sb2[nl + 1];
            if (tok0 >= 0) {
                float* orow = out + (size_t)tok0 * DIM + c0 + nl;
                atomicAdd(orow,     (acc[i][j][0] + bA) * wt0);
                atomicAdd(orow + 1, (acc[i][j][1] + bB) * wt0);
            }
            if (tok1 >= 0) {
                float* orow = out + (size_t)tok1 * DIM + c0 + nl;
                atomicAdd(orow,     (acc[i][j][2] + bA) * wt1);
                atomicAdd(orow + 1, (acc[i][j][3] + bB) * wt1);
            }
        }
    }
}

// ---------------- launcher ----------------
extern "C" void kernel_launch(void* const* d_in, const int* in_sizes, int n_in,
                              void* d_out, int out_size) {
    const float* x  = (const float*)d_in[0];
    const float* Wg = (const float*)d_in[1];
    const float* bg = (const float*)d_in[2];
    const float* W1 = (const float*)d_in[3];
    const float* b1 = (const float*)d_in[4];
    const float* W2 = (const float*)d_in[5];
    const float* b2 = (const float*)d_in[6];
    float* out = (float*)d_out;

    const int SMEM = NSTAGE * ST_STRIDE;  // 64 KB
    cudaFuncSetAttribute(k_mm1, cudaFuncAttributeMaxDynamicSharedMemorySize, SMEM);
    cudaFuncSetAttribute(k_mm2, cudaFuncAttributeMaxDynamicSharedMemorySize, SMEM);

    k_zero<<<1024, 256>>>(out, NTOK * DIM);
    k_conv_w1<<<dim3(64, 16, NE), dim3(32, 8)>>>(W1);
    k_conv_w2<<<dim3(16, 32, NE), dim3(32, 8)>>>(W2);
    k_gate<<<NTOK / 8, 256>>>(x, Wg, bg);
    k_mm1<<<dim3(MAXTILES, DFFV / 64), 256, SMEM>>>(b1);
    k_mm2<<<dim3(MAXTILES, DIM / 128), 256, SMEM>>>(b2, out);
}

// round 16
// speedup vs baseline: 1.1257x; 1.0238x over previous
#include <cuda_runtime.h>
#include <cuda_fp16.h>
#include <math.h>
#include <stdint.h>

#define NTOK 8192
#define DIM 512
#define DFFV 1024
#define NE 8
#define TM 128
#define MAXTILES 136

// ---------------- device scratch ----------------
__device__ int   g_cnt[NE];
__device__ int   g_tokid[NE * NTOK];      // id -> token
__device__ float g_wtid [NE * NTOK];      // id -> routing weight
__device__ __half g_x  [(size_t)NE * NTOK * DIM];       // gathered x fp16
__device__ __half g_w1 [(size_t)NE * 2 * DFFV * DIM];   // W1^T fp16
__device__ __half g_w2 [(size_t)NE * DIM * DFFV];       // W2^T fp16
__device__ __half g_a  [(size_t)NE * NTOK * DFFV];      // act fp16

// ---------------- helpers ----------------
__device__ __forceinline__ uint32_t smem_u32(const void* p) {
    uint32_t a;
    asm("{ .reg .u64 t; cvta.to.shared.u64 t, %1; cvt.u32.u64 %0, t; }" : "=r"(a) : "l"(p));
    return a;
}
#define CPA16(sa, ga) asm volatile("cp.async.cg.shared.global [%0], [%1], 16;"::"r"(sa),"l"(ga):"memory")
#define CPA_COMMIT()  asm volatile("cp.async.commit_group;":::"memory")
#define CPA_WAIT2()   asm volatile("cp.async.wait_group 2;":::"memory")

#define LDSM_X4(r, addr) \
    asm volatile("ldmatrix.sync.aligned.m8n8.x4.shared.b16 {%0,%1,%2,%3}, [%4];" \
        : "=r"((r)[0]), "=r"((r)[1]), "=r"((r)[2]), "=r"((r)[3]) : "r"(addr))

#define MMA_F16(d, a, b0, b1) \
    asm volatile("mma.sync.aligned.m16n8k16.row.col.f32.f16.f16.f32 " \
        "{%0,%1,%2,%3},{%4,%5,%6,%7},{%8,%9},{%0,%1,%2,%3};" \
        : "+f"((d)[0]), "+f"((d)[1]), "+f"((d)[2]), "+f"((d)[3]) \
        : "r"((a)[0]), "r"((a)[1]), "r"((a)[2]), "r"((a)[3]), "r"(b0), "r"(b1))

__device__ __forceinline__ uint32_t sw64(uint32_t off) {
    return off ^ ((off >> 3) & 0x30);
}

// locate expert + tile base from g_cnt
__device__ __forceinline__ bool tile_lookup(int tile, int& e, int& m0, int& cnt) {
    int base = 0;
    for (e = 0; e < NE; e++) {
        int c = g_cnt[e];
        int nt = (c + TM - 1) / TM;
        if (tile < base + nt) { m0 = (tile - base) * TM; cnt = c; return true; }
        base += nt;
    }
    return false;
}

// ---------------- K0/K1: fused transpose+fp16 convert (vectorized) ----------------
// src [R][C] fp32 row-major -> dst [C][R] fp16.  Tile 64x64, float4 in, uint4 out.
__global__ __launch_bounds__(256) void k_convT(const float* __restrict__ srcAll,
                                               __half* __restrict__ dstAll,
                                               int R, int C) {
    if (blockIdx.x == 0 && blockIdx.y == 0 && blockIdx.z == 0 && threadIdx.x < NE)
        g_cnt[threadIdx.x] = 0;   // idempotent; both conv launches precede k_gate

    const float* src = srcAll + (size_t)blockIdx.z * R * C;
    __half* dst = dstAll + (size_t)blockIdx.z * R * C;
    int r0 = blockIdx.y * 64, c0 = blockIdx.x * 64;

    __shared__ float ts[64][65];
    int tid = threadIdx.x;
#pragma unroll
    for (int p = 0; p < 4; p++) {
        int u = tid + p * 256;
        int r = u >> 4, cq = u & 15;
        float4 v = *(const float4*)(src + (size_t)(r0 + r) * C + c0 + cq * 4);
        ts[r][cq * 4 + 0] = v.x;
        ts[r][cq * 4 + 1] = v.y;
        ts[r][cq * 4 + 2] = v.z;
        ts[r][cq * 4 + 3] = v.w;
    }
    __syncthreads();
#pragma unroll
    for (int p = 0; p < 2; p++) {
        int u = tid + p * 256;
        int n = u >> 3, seg = u & 7;
        __half h[8];
#pragma unroll
        for (int i = 0; i < 8; i++) h[i] = __float2half(ts[seg * 8 + i][n]);
        *(uint4*)(dst + (size_t)(c0 + n) * R + r0 + seg * 8) = *(uint4*)h;
    }
}

// ---------------- K2: gating + fused x->fp16 scatter + out-row zeroing ----------------
__global__ __launch_bounds__(256) void k_gate(const float* __restrict__ x,
                                              const float* __restrict__ Wg,
                                              const float* __restrict__ bg,
                                              float* __restrict__ out) {
    __shared__ float wgsT[NE][DIM];
    int t = threadIdx.x;
    for (int i = t; i < DIM * NE; i += 256) wgsT[i & 7][i >> 3] = Wg[i];
    __syncthreads();

    int warp = t >> 5, lane = t & 31;
    int tok = blockIdx.x * 8 + warp;

    float acc[NE];
#pragma unroll
    for (int e = 0; e < NE; e++) acc[e] = 0.f;
    const float4* xr = (const float4*)(x + (size_t)tok * DIM);
    float4 xv[4];
#pragma unroll
    for (int j = 0; j < 4; j++) {
        xv[j] = xr[lane + j * 32];
        int d = (lane + j * 32) * 4;
#pragma unroll
        for (int e = 0; e < NE; e++) {
            float4 w = *(const float4*)&wgsT[e][d];
            acc[e] += xv[j].x * w.x + xv[j].y * w.y + xv[j].z * w.z + xv[j].w * w.w;
        }
    }
#pragma unroll
    for (int e = 0; e < NE; e++)
#pragma unroll
        for (int o = 16; o; o >>= 1) acc[e] += __shfl_xor_sync(0xFFFFFFFFu, acc[e], o);

    int id1 = 0, id2 = 0;
    if (lane == 0) {
        float lg[NE];
#pragma unroll
        for (int e = 0; e < NE; e++) lg[e] = acc[e] + bg[e];
        int i1 = 0;
#pragma unroll
        for (int e = 1; e < NE; e++) if (lg[e] > lg[i1]) i1 = e;
        int i2 = (i1 == 0) ? 1 : 0;
#pragma unroll
        for (int e = 0; e < NE; e++) if (e != i1 && lg[e] > lg[i2]) i2 = e;
        float tt = expf(lg[i2] - lg[i1]);
        float w1 = 1.f / (1.f + tt);
        float w2 = tt / (1.f + tt);
        int p1 = atomicAdd(&g_cnt[i1], 1);
        int p2 = atomicAdd(&g_cnt[i2], 1);
        id1 = i1 * NTOK + p1;
        id2 = i2 * NTOK + p2;
        g_tokid[id1] = tok; g_wtid[id1] = w1;
        g_tokid[id2] = tok; g_wtid[id2] = w2;
    }
    id1 = __shfl_sync(0xFFFFFFFFu, id1, 0);
    id2 = __shfl_sync(0xFFFFFFFFu, id2, 0);

#pragma unroll
    for (int j = 0; j < 4; j++) {
        __half h[4] = {__float2half(xv[j].x), __float2half(xv[j].y),
                       __float2half(xv[j].z), __float2half(xv[j].w)};
        int c = (lane + j * 32) * 4;
        *(uint2*)(g_x + (size_t)id1 * DIM + c) = *(uint2*)h;
        *(uint2*)(g_x + (size_t)id2 * DIM + c) = *(uint2*)h;
    }

    // zero this token's output row (consumed by mm2's atomic scatter, later in stream)
    float4 z4 = make_float4(0.f, 0.f, 0.f, 0.f);
#pragma unroll
    for (int j = 0; j < 4; j++)
        *(float4*)(out + (size_t)tok * DIM + (lane + j * 32) * 4) = z4;
}

// ==================== GEMM core (R10-proven: 8 warps 2x4, warp tile 64x32) ====================
// tile 128x128, BK=32, 4 stages, wait_group 2
#define ST_A  0
#define ST_B  8192
#define ST_STRIDE 16384
#define NSTAGE 4

__device__ __forceinline__ void compute_chunk(uint32_t sbase, int stage,
                                              int wm, int wn, int lane,
                                              float acc[4][4][4]) {
    uint32_t aOff = sbase + stage * ST_STRIDE + ST_A;
    uint32_t bOff = sbase + stage * ST_STRIDE + ST_B;
    int lr = lane & 15, lh = lane >> 4;
#pragma unroll
    for (int ks = 0; ks < 2; ks++) {
        uint32_t bh[8];
#pragma unroll
        for (int jp = 0; jp < 2; jp++) {
            uint32_t o = sw64((uint32_t)(wn * 32 + jp * 16 + lr) * 64 + ks * 32 + lh * 16);
            LDSM_X4(&bh[jp * 4], bOff + o);
        }
#pragma unroll
        for (int i = 0; i < 4; i++) {
            uint32_t o = sw64((uint32_t)(wm * 64 + i * 16 + lr) * 64 + ks * 32 + lh * 16);
            uint32_t af[4];
            LDSM_X4(af, aOff + o);
#pragma unroll
            for (int j = 0; j < 4; j++) {
                int jp = j >> 1, idx = j & 1;
                MMA_F16(acc[i][j], af, bh[jp * 4 + idx], bh[jp * 4 + idx + 2]);
            }
        }
    }
}

// ---------------- K3: GEMM1 + SiLU*mul -> act fp16 ----------------
__global__ __launch_bounds__(256, 2) void k_mm1(const float* __restrict__ b1) {
    int e, m0, cnt;
    if (!tile_lookup(blockIdx.x, e, m0, cnt)) return;
    int f0 = blockIdx.y * 64;
    int abase = e * NTOK + m0;

    extern __shared__ __align__(1024) char dsm[];
    __shared__ float sb1a[64], sb1g[64];
    uint32_t sbase = smem_u32(dsm);

    int tid = threadIdx.x, wid = tid >> 5, lane = tid & 31;
    int wm = wid >> 2, wn = wid & 3;

    if (tid < 64)       sb1a[tid] = b1[(size_t)e * 2 * DFFV + f0 + tid];
    else if (tid < 128) sb1g[tid - 64] = b1[(size_t)e * 2 * DFFV + DFFV + f0 + tid - 64];

    const __half* w1 = g_w1 + (size_t)e * 2 * DFFV * DIM;

    float acc[4][4][4];
#pragma unroll
    for (int i = 0; i < 4; i++)
#pragma unroll
        for (int j = 0; j < 4; j++)
#pragma unroll
            for (int q = 0; q < 4; q++) acc[i][j][q] = 0.f;

    auto load_chunk = [&](int stage, int c) {
        uint32_t base = sbase + stage * ST_STRIDE;
        int k0 = c * 32;
#pragma unroll
        for (int u = tid; u < 512; u += 256) {
            int r = u >> 2, cs = u & 3;
            uint32_t sw = sw64((uint32_t)r * 64 + cs * 16);
            CPA16(base + ST_A + sw, g_x + (size_t)(abase + r) * DIM + k0 + cs * 8);
            int nw = (r & 1) ? (DFFV + f0 + (r >> 1)) : (f0 + (r >> 1));
            CPA16(base + ST_B + sw, w1 + (size_t)nw * DIM + k0 + cs * 8);
        }
    };

    const int NC = DIM / 32;  // 16
    load_chunk(0, 0); CPA_COMMIT();
    load_chunk(1, 1); CPA_COMMIT();
    load_chunk(2, 2); CPA_COMMIT();
    CPA_WAIT2();
    __syncthreads();
    for (int c = 0; c < NC; c++) {
        if (c + 3 < NC) load_chunk((c + 3) % NSTAGE, c + 3);
        CPA_COMMIT();
        compute_chunk(sbase, c % NSTAGE, wm, wn, lane, acc);
        CPA_WAIT2();
        __syncthreads();
    }

    // bias + silu*mul in registers
#pragma unroll
    for (int i = 0; i < 4; i++)
#pragma unroll
        for (int j = 0; j < 4; j++) {
            int fl = wn * 16 + j * 4 + (lane & 3);
            float ba = sb1a[fl], bg = sb1g[fl];
            float a0 = acc[i][j][0] + ba, gg0 = acc[i][j][1] + bg;
            float a1 = acc[i][j][2] + ba, gg1 = acc[i][j][3] + bg;
            acc[i][j][0] = gg0 * a0 / (1.f + __expf(-a0));
            acc[i][j][2] = gg1 * a1 / (1.f + __expf(-a1));
        }

    // staged store through smem [128][72] halfs, 16B coalesced writes
    __half* st = (__half*)dsm;
#pragma unroll
    for (int i = 0; i < 4; i++) {
        int r0 = wm * 64 + i * 16 + (lane >> 2);
#pragma unroll
        for (int j = 0; j < 4; j++) {
            int fl = wn * 16 + j * 4 + (lane & 3);
            st[r0 * 72 + fl] = __float2half(acc[i][j][0]);
            st[(r0 + 8) * 72 + fl] = __float2half(acc[i][j][2]);
        }
    }
    __syncthreads();
#pragma unroll
    for (int u = tid; u < 1024; u += 256) {
        int r = u >> 3, seg = u & 7;
        if (m0 + r < cnt) {
            *(uint4*)(g_a + (size_t)(abase + r) * DFFV + f0 + seg * 8) =
                *(uint4*)&st[r * 72 + seg * 8];
        }
    }
}

// ---------------- K4: GEMM2 + fused weighted scatter (2 atomics/elem, deterministic) ----------------
__global__ __launch_bounds__(256, 2) void k_mm2(const float* __restrict__ b2,
                                                float* __restrict__ out) {
    int e, m0, cnt;
    if (!tile_lookup(blockIdx.x, e, m0, cnt)) return;
    int c0 = blockIdx.y * 128;
    int abase = e * NTOK + m0;

    extern __shared__ __align__(1024) char dsm[];
    __shared__ float sb2[128];
    __shared__ int   s_tok[128];
    __shared__ float s_wt[128];
    uint32_t sbase = smem_u32(dsm);

    int tid = threadIdx.x, wid = tid >> 5, lane = tid & 31;
    int wm = wid >> 2, wn = wid & 3;

    if (tid < 128) {
        sb2[tid] = b2[(size_t)e * DIM + c0 + tid];
        int ok = (m0 + tid) < cnt;
        s_tok[tid] = ok ? g_tokid[abase + tid] : -1;
        s_wt[tid]  = ok ? g_wtid[abase + tid] : 0.f;
    }

    const __half* w2 = g_w2 + (size_t)e * DIM * DFFV;

    float acc[4][4][4];
#pragma unroll
    for (int i = 0; i < 4; i++)
#pragma unroll
        for (int j = 0; j < 4; j++)
#pragma unroll
            for (int q = 0; q < 4; q++) acc[i][j][q] = 0.f;

    auto load_chunk = [&](int stage, int c) {
        uint32_t base = sbase + stage * ST_STRIDE;
        int k0 = c * 32;
#pragma unroll
        for (int u = tid; u < 512; u += 256) {
            int r = u >> 2, cs = u & 3;
            uint32_t sw = sw64((uint32_t)r * 64 + cs * 16);
            CPA16(base + ST_A + sw, g_a + (size_t)(abase + r) * DFFV + k0 + cs * 8);
            CPA16(base + ST_B + sw, w2 + (size_t)(c0 + r) * DFFV + k0 + cs * 8);
        }
    };

    const int NC = DFFV / 32;  // 32
    load_chunk(0, 0); CPA_COMMIT();
    load_chunk(1, 1); CPA_COMMIT();
    load_chunk(2, 2); CPA_COMMIT();
    CPA_WAIT2();
    __syncthreads();
    for (int c = 0; c < NC; c++) {
        if (c + 3 < NC) load_chunk((c + 3) % NSTAGE, c + 3);
        CPA_COMMIT();
        compute_chunk(sbase, c % NSTAGE, wm, wn, lane, acc);
        CPA_WAIT2();
        __syncthreads();
    }

    // epilogue: (acc + b2) * wt, atomicAdd to out (exactly 2 adds/elem -> deterministic)
#pragma unroll
    for (int i = 0; i < 4; i++) {
        int r0 = wm * 64 + i * 16 + (lane >> 2);
        int r1 = r0 + 8;
        int tok0 = s_tok[r0], tok1 = s_tok[r1];
        float wt0 = s_wt[r0], wt1 = s_wt[r1];
#pragma unroll
        for (int j = 0; j < 4; j++) {
            int nl = wn * 32 + j * 8 + (lane & 3) * 2;
            float bA = sb2[nl], bB = sb2[nl + 1];
            if (tok0 >= 0) {
                float* orow = out + (size_t)tok0 * DIM + c0 + nl;
                atomicAdd(orow,     (acc[i][j][0] + bA) * wt0);
                atomicAdd(orow + 1, (acc[i][j][1] + bB) * wt0);
            }
            if (tok1 >= 0) {
                float* orow = out + (size_t)tok1 * DIM + c0 + nl;
                atomicAdd(orow,     (acc[i][j][2] + bA) * wt1);
                atomicAdd(orow + 1, (acc[i][j][3] + bB) * wt1);
            }
        }
    }
}

// ---------------- launcher ----------------
extern "C" void kernel_launch(void* const* d_in, const int* in_sizes, int n_in,
                              void* d_out, int out_size) {
    const float* x  = (const float*)d_in[0];
    const float* Wg = (const float*)d_in[1];
    const float* bg = (const float*)d_in[2];
    const float* W1 = (const float*)d_in[3];
    const float* b1 = (const float*)d_in[4];
    const float* W2 = (const float*)d_in[5];
    const float* b2 = (const float*)d_in[6];
    float* out = (float*)d_out;

    const int SMEM = NSTAGE * ST_STRIDE;  // 64 KB
    cudaFuncSetAttribute(k_mm1, cudaFuncAttributeMaxDynamicSharedMemorySize, SMEM);
    cudaFuncSetAttribute(k_mm2, cudaFuncAttributeMaxDynamicSharedMemorySize, SMEM);

    // W1: [512][2048] -> g_w1 [2048][512];  W2: [1024][512] -> g_w2 [512][1024]
    __half* d_w1;  cudaGetSymbolAddress((void**)&d_w1, g_w1);
    __half* d_w2;  cudaGetSymbolAddress((void**)&d_w2, g_w2);
    k_convT<<<dim3(2 * DFFV / 64, DIM / 64, NE), 256>>>(W1, d_w1, DIM, 2 * DFFV);
    k_convT<<<dim3(DIM / 64, DFFV / 64, NE), 256>>>(W2, d_w2, DFFV, DIM);
    k_gate<<<NTOK / 8, 256>>>(x, Wg, bg, out);
    k_mm1<<<dim3(MAXTILES, DFFV / 64), 256, SMEM>>>(b1);
    k_mm2<<<dim3(MAXTILES, DIM / 128), 256, SMEM>>>(b2, out);
}